// round 1
// baseline (speedup 1.0000x reference)
#include <cuda_runtime.h>
#include <cstdint>
#include <cstddef>

// CTRNN: out[t,b,j] = h_t[b,j];  h_t = relu(0.8*h_{t-1} + 0.2*(x_t@W_in^T + b_in + h_{t-1}@W_hh^T + b_hh + noise_t))
// T=512, B=256, I=64, H=256. Batch-independent recurrence -> persistent kernel,
// 128 CTAs x 256 threads, 2 batches per CTA, no inter-CTA sync ever.
//
// Augmented K = 64 (input) + 256 (recurrent) = 320 rows.
//   rows 0..191  : in shared memory, layout [chunk(4k)][j] as 16B slots (conflict-free LDS.128)
//   rows 192..319: in registers (64 x u64 packed pairs per thread = 128 floats)
// All math fp32; inner product uses packed fma.rn.f32x2 (2 FMA per issue slot).

#define T_STEPS 512
#define BATCH   256
#define IN_SZ   64
#define HID     256
#define KAUG    320
#define SMEM_CHUNKS 48            // 48 chunks * 4 k = 192 rows in smem
#define SMEM_K  (SMEM_CHUNKS * 4)
#define REG_U64 64                // 128 k-rows in registers (as 64 packed u64)
#define NCTA    (BATCH / 2)
#define NTHR    256

typedef unsigned long long u64;

// smem: W region [SMEM_CHUNKS][256] of 16B, then hA[KAUG], pad, hB[KAUG]
#define SMEM_W_BYTES  (SMEM_CHUNKS * NTHR * 16)
#define HA_OFF        (SMEM_W_BYTES)
#define HB_OFF        (HA_OFF + (KAUG + 16) * 4)     // 16-float pad, keeps 16B alignment
#define SMEM_TOTAL    (HB_OFF + (KAUG + 16) * 4)

__device__ __forceinline__ u64 fma2(u64 a, u64 b, u64 c) {
    u64 d;
    asm("fma.rn.f32x2 %0, %1, %2, %3;" : "=l"(d) : "l"(a), "l"(b), "l"(c));
    return d;
}
__device__ __forceinline__ u64 add2(u64 a, u64 b) {
    u64 d;
    asm("add.rn.f32x2 %0, %1, %2;" : "=l"(d) : "l"(a), "l"(b));
    return d;
}
__device__ __forceinline__ float sum2(u64 a) {
    float lo, hi;
    asm("mov.b64 {%0, %1}, %2;" : "=f"(lo), "=f"(hi) : "l"(a));
    return lo + hi;
}

__global__ void __launch_bounds__(NTHR, 1)
ctrnn_persistent_kernel(const float* __restrict__ x,
                        const float* __restrict__ h0,
                        const float* __restrict__ noise,
                        const float* __restrict__ Win,
                        const float* __restrict__ bin,
                        const float* __restrict__ Whh,
                        const float* __restrict__ bhh,
                        float* __restrict__ out,
                        float* __restrict__ hlast)
{
    extern __shared__ unsigned char smem_raw[];
    ulonglong2* Wsm = reinterpret_cast<ulonglong2*>(smem_raw);
    float* hA = reinterpret_cast<float*>(smem_raw + HA_OFF);
    float* hB = reinterpret_cast<float*>(smem_raw + HB_OFF);

    const int j  = threadIdx.x;           // output unit owned by this thread
    const int b0 = blockIdx.x * 2;
    const int b1 = b0 + 1;

    // ---- one-time init: stage W into smem ([chunk][j], 16B slots) ----
    // chunk c<16 -> W_in[j][4c..4c+3]; c>=16 -> W_hh[j][4(c-16)..]
    #pragma unroll 4
    for (int c = 0; c < SMEM_CHUNKS; ++c) {
        float4 v;
        if (c < IN_SZ / 4) v = *reinterpret_cast<const float4*>(&Win[j * IN_SZ + 4 * c]);
        else               v = *reinterpret_cast<const float4*>(&Whh[j * HID + 4 * (c - IN_SZ / 4)]);
        *reinterpret_cast<float4*>(&Wsm[c * NTHR + j]) = v;
    }

    // ---- one-time init: register-resident W rows (aug-k 192..319 = W_hh rows 128..255) ----
    u64 wreg[REG_U64];
    #pragma unroll
    for (int r = 0; r < REG_U64; ++r)
        wreg[r] = *reinterpret_cast<const u64*>(&Whh[j * HID + (SMEM_K - IN_SZ) + 2 * r]);

    const float bsum = bin[j] + bhh[j];

    // ---- initial state + x(t=0) staged into augmented vectors ----
    hA[IN_SZ + j] = h0[b0 * HID + j];
    hB[IN_SZ + j] = h0[b1 * HID + j];
    if (j < IN_SZ)            hA[j]          = x[(size_t)b0 * IN_SZ + j];
    else if (j < 2 * IN_SZ)   hB[j - IN_SZ]  = x[(size_t)b1 * IN_SZ + (j - IN_SZ)];
    float nb = noise[j] + bsum;
    __syncthreads();

    for (int t = 0; t < T_STEPS; ++t) {
        // prefetch next step's x and noise (latency hidden under ~3K-cycle body)
        const int tn = (t + 1 < T_STEPS) ? t + 1 : t;
        float xAn = 0.f, xBn = 0.f;
        if (j < IN_SZ)          xAn = x[((size_t)tn * BATCH + b0) * IN_SZ + j];
        else if (j < 2 * IN_SZ) xBn = x[((size_t)tn * BATCH + b1) * IN_SZ + (j - IN_SZ)];
        const float nb_next = noise[(size_t)tn * HID + j] + bsum;

        u64 aA0 = 0, aA1 = 0, aB0 = 0, aB1 = 0;
        const ulonglong2* wp = Wsm + j;

        #pragma unroll
        for (int c = 0; c < SMEM_CHUNKS; ++c) {
            ulonglong2 w  = wp[c * NTHR];
            ulonglong2 ha = *reinterpret_cast<const ulonglong2*>(&hA[4 * c]);
            ulonglong2 hb = *reinterpret_cast<const ulonglong2*>(&hB[4 * c]);
            aA0 = fma2(w.x, ha.x, aA0);  aA1 = fma2(w.y, ha.y, aA1);
            aB0 = fma2(w.x, hb.x, aB0);  aB1 = fma2(w.y, hb.y, aB1);
        }
        #pragma unroll
        for (int i = 0; i < REG_U64 / 2; ++i) {
            ulonglong2 ha = *reinterpret_cast<const ulonglong2*>(&hA[SMEM_K + 4 * i]);
            ulonglong2 hb = *reinterpret_cast<const ulonglong2*>(&hB[SMEM_K + 4 * i]);
            aA0 = fma2(wreg[2 * i], ha.x, aA0);  aA1 = fma2(wreg[2 * i + 1], ha.y, aA1);
            aB0 = fma2(wreg[2 * i], hb.x, aB0);  aB1 = fma2(wreg[2 * i + 1], hb.y, aB1);
        }

        const float preA = sum2(add2(aA0, aA1)) + nb;
        const float preB = sum2(add2(aB0, aB1)) + nb;
        const float hAo = hA[IN_SZ + j];
        const float hBo = hB[IN_SZ + j];
        const float hnA = fmaxf(hAo * 0.8f + preA * 0.2f, 0.f);
        const float hnB = fmaxf(hBo * 0.8f + preB * 0.2f, 0.f);

        if (out) {
            out[((size_t)t * BATCH + b0) * HID + j] = hnA;
            out[((size_t)t * BATCH + b1) * HID + j] = hnB;
        }

        __syncthreads();                       // all reads of old h done
        hA[IN_SZ + j] = hnA;
        hB[IN_SZ + j] = hnB;
        if (j < IN_SZ)            hA[j]         = xAn;
        else if (j < 2 * IN_SZ)   hB[j - IN_SZ] = xBn;
        nb = nb_next;
        __syncthreads();                       // new h/x visible
    }

    if (hlast) {
        hlast[b0 * HID + j] = hA[IN_SZ + j];
        hlast[b1 * HID + j] = hB[IN_SZ + j];
    }
}

extern "C" void kernel_launch(void* const* d_in, const int* in_sizes, int n_in,
                              void* d_out, int out_size)
{
    const float* x     = (const float*)d_in[0];   // [512,256,64]
    const float* h0    = (const float*)d_in[1];   // [256,256]
    const float* noise = (const float*)d_in[2];   // [512,256]
    const float* Win   = (const float*)d_in[3];   // [256,64]
    const float* bin   = (const float*)d_in[4];   // [256]
    const float* Whh   = (const float*)d_in[5];   // [256,256]
    const float* bhh   = (const float*)d_in[6];   // [256]

    const size_t TBH = (size_t)T_STEPS * BATCH * HID;
    const size_t BH  = (size_t)BATCH * HID;

    float* out   = nullptr;
    float* hlast = nullptr;
    if ((size_t)out_size >= TBH) {
        out = (float*)d_out;
        if ((size_t)out_size >= TBH + BH) hlast = (float*)d_out + TBH;
    } else {
        hlast = (float*)d_out;   // degenerate: only final state requested
    }

    static bool attr_set = false;
    if (!attr_set) {
        cudaFuncSetAttribute(ctrnn_persistent_kernel,
                             cudaFuncAttributeMaxDynamicSharedMemorySize, SMEM_TOTAL);
        attr_set = true;
    }

    ctrnn_persistent_kernel<<<NCTA, NTHR, SMEM_TOTAL>>>(
        x, h0, noise, Win, bin, Whh, bhh, out, hlast);
}

// round 2
// speedup vs baseline: 1.6984x; 1.6984x over previous
#include <cuda_runtime.h>
#include <cstdint>
#include <cstddef>

// CTRNN persistent kernel, round 2: k-split across 2 warp-groups.
// T=512, B=256, I=64, H=256. 128 CTAs x 512 threads, 2 batches/CTA.
// Augmented K = 320 (64 input + 256 recurrent).
//   group 0 (threads 0..255):   aug rows   0..159
//   group 1 (threads 256..511): aug rows 160..319
// Per group: 96 rows from smem (24 chunks of 4 rows, [chunk][j] 16B slots),
//            64 rows register-resident (32 packed u64 per thread).
// Partial sums exchanged via smem; group 0 finalizes batch A, group 1 batch B.
// Double-buffered augmented state vectors (x_t | h_t), 2 syncthreads/step.

#define T_STEPS 512
#define BATCH   256
#define IN_SZ   64
#define HID     256
#define KAUG    320
#define NTHR    512
#define NCTA    (BATCH / 2)

#define CHUNKS_PER_GROUP 24           // 96 smem rows per group
#define SMEM_ROWS        96
#define REG_U64          32           // 64 reg rows per group
#define TOTAL_CHUNKS     (2 * CHUNKS_PER_GROUP)

typedef unsigned long long u64;

// smem layout
#define SMEM_W_BYTES  (TOTAL_CHUNKS * HID * 16)            // 48*256*16 = 196608
#define BUF_FLOATS    352                                  // 320 + pad, 16B-multiple
#define HBUF_OFF      SMEM_W_BYTES
// buffers: [buf(2)][batch(2)][BUF_FLOATS]
#define RED_OFF       (HBUF_OFF + 2 * 2 * BUF_FLOATS * 4)
#define SMEM_TOTAL    (RED_OFF + 2 * HID * 4)              // redA, redB

__device__ __forceinline__ u64 fma2(u64 a, u64 b, u64 c) {
    u64 d;
    asm("fma.rn.f32x2 %0, %1, %2, %3;" : "=l"(d) : "l"(a), "l"(b), "l"(c));
    return d;
}
__device__ __forceinline__ u64 add2(u64 a, u64 b) {
    u64 d;
    asm("add.rn.f32x2 %0, %1, %2;" : "=l"(d) : "l"(a), "l"(b));
    return d;
}
__device__ __forceinline__ float sum2(u64 a) {
    float lo, hi;
    asm("mov.b64 {%0, %1}, %2;" : "=f"(lo), "=f"(hi) : "l"(a));
    return lo + hi;
}

__global__ void __launch_bounds__(NTHR, 1)
ctrnn_ksplit_kernel(const float* __restrict__ x,
                    const float* __restrict__ h0,
                    const float* __restrict__ noise,
                    const float* __restrict__ Win,
                    const float* __restrict__ bin,
                    const float* __restrict__ Whh,
                    const float* __restrict__ bhh,
                    float* __restrict__ out,
                    float* __restrict__ hlast)
{
    extern __shared__ unsigned char smem_raw[];
    ulonglong2* Wsm = reinterpret_cast<ulonglong2*>(smem_raw);
    float* hbuf = reinterpret_cast<float*>(smem_raw + HBUF_OFF);  // [2][2][BUF_FLOATS]
    float* redA = reinterpret_cast<float*>(smem_raw + RED_OFF);   // batch-A partial from g1
    float* redB = redA + HID;                                     // batch-B partial from g0

    const int tid = threadIdx.x;
    const int g   = tid >> 8;          // warp-group: 0 or 1
    const int j   = tid & 255;         // output unit
    const int b0  = blockIdx.x * 2;
    const int b1  = b0 + 1;
    const int myb = g == 0 ? b0 : b1;  // batch this group finalizes

    // ---- stage W into smem: global chunk cg owns aug rows 4cg..4cg+3 ----
    // cg 0..15  -> Win[j][4cg..]          (aug 0..63)
    // cg 16..23 -> Whh[j][4(cg-16)..]     (aug 64..95,  hh cols 0..31)
    // cg 24..47 -> Whh[j][96+4(cg-24)..]  (aug 160..255, hh cols 96..191)
    for (int cg = g * CHUNKS_PER_GROUP; cg < (g + 1) * CHUNKS_PER_GROUP; ++cg) {
        float4 v;
        if (cg < 16)       v = *reinterpret_cast<const float4*>(&Win[j * IN_SZ + 4 * cg]);
        else if (cg < 24)  v = *reinterpret_cast<const float4*>(&Whh[j * HID + 4 * (cg - 16)]);
        else               v = *reinterpret_cast<const float4*>(&Whh[j * HID + 96 + 4 * (cg - 24)]);
        *reinterpret_cast<float4*>(&Wsm[cg * HID + j]) = v;
    }

    // ---- register W rows ----
    // g=0: aug 96..159  = hh cols 32..95   ; g=1: aug 256..319 = hh cols 192..255
    const int reg_base = g == 0 ? 32 : 192;
    u64 wreg[REG_U64];
    #pragma unroll
    for (int r = 0; r < REG_U64; ++r)
        wreg[r] = *reinterpret_cast<const u64*>(&Whh[j * HID + reg_base + 2 * r]);

    const float bsum = bin[j] + bhh[j];

    // ---- initial staging: buffer 0 holds (x_0 | h_0) for both batches ----
    float* bufA0 = hbuf;                  // [0][A]
    float* bufB0 = hbuf + BUF_FLOATS;     // [0][B]
    if (g == 0) {
        bufA0[IN_SZ + j] = h0[b0 * HID + j];
        if (j < IN_SZ) bufA0[j] = x[(size_t)b0 * IN_SZ + j];
    } else {
        bufB0[IN_SZ + j] = h0[b1 * HID + j];
        if (j < IN_SZ) bufB0[j] = x[(size_t)b1 * IN_SZ + j];
    }
    float nb = noise[j] + bsum;
    __syncthreads();

    const int smem_aug = g * 160;         // start of this group's smem-rows slice
    const ulonglong2* wp = Wsm + (size_t)(g * CHUNKS_PER_GROUP) * HID + j;

    for (int t = 0; t < T_STEPS; ++t) {
        const float* bufA = hbuf + ((t & 1) ? 2 * BUF_FLOATS : 0);
        const float* bufB = bufA + BUF_FLOATS;
        float* bufAn = hbuf + ((t & 1) ? 0 : 2 * BUF_FLOATS);
        float* bufBn = bufAn + BUF_FLOATS;

        // prefetch next step's x (own batch) and noise
        const int tn = (t + 1 < T_STEPS) ? t + 1 : t;
        float xn = 0.f;
        if (j < IN_SZ) xn = x[((size_t)tn * BATCH + myb) * IN_SZ + j];
        const float nb_next = noise[(size_t)tn * HID + j] + bsum;

        const float* hAc = bufA + smem_aug;
        const float* hBc = bufB + smem_aug;

        u64 aA0 = 0, aA1 = 0, aB0 = 0, aB1 = 0;
        #pragma unroll
        for (int c = 0; c < CHUNKS_PER_GROUP; ++c) {
            ulonglong2 w  = wp[(size_t)c * HID];
            ulonglong2 ha = *reinterpret_cast<const ulonglong2*>(&hAc[4 * c]);
            ulonglong2 hb = *reinterpret_cast<const ulonglong2*>(&hBc[4 * c]);
            aA0 = fma2(w.x, ha.x, aA0);  aA1 = fma2(w.y, ha.y, aA1);
            aB0 = fma2(w.x, hb.x, aB0);  aB1 = fma2(w.y, hb.y, aB1);
        }
        #pragma unroll
        for (int i = 0; i < REG_U64 / 2; ++i) {
            ulonglong2 ha = *reinterpret_cast<const ulonglong2*>(&hAc[SMEM_ROWS + 4 * i]);
            ulonglong2 hb = *reinterpret_cast<const ulonglong2*>(&hBc[SMEM_ROWS + 4 * i]);
            aA0 = fma2(wreg[2 * i], ha.x, aA0);  aA1 = fma2(wreg[2 * i + 1], ha.y, aA1);
            aB0 = fma2(wreg[2 * i], hb.x, aB0);  aB1 = fma2(wreg[2 * i + 1], hb.y, aB1);
        }

        const float ownA = sum2(add2(aA0, aA1));
        const float ownB = sum2(add2(aB0, aB1));

        // exchange the cross partial (each group ships the batch it does NOT finalize)
        if (g == 0) redB[j] = ownB;
        else        redA[j] = ownA;
        __syncthreads();

        if (g == 0) {
            const float pre  = ownA + redA[j] + nb;
            const float hold = bufA[IN_SZ + j];
            const float hn   = fmaxf(hold * 0.8f + pre * 0.2f, 0.f);
            if (out) out[((size_t)t * BATCH + b0) * HID + j] = hn;
            bufAn[IN_SZ + j] = hn;
            if (j < IN_SZ) bufAn[j] = xn;
        } else {
            const float pre  = ownB + redB[j] + nb;
            const float hold = bufB[IN_SZ + j];
            const float hn   = fmaxf(hold * 0.8f + pre * 0.2f, 0.f);
            if (out) out[((size_t)t * BATCH + b1) * HID + j] = hn;
            bufBn[IN_SZ + j] = hn;
            if (j < IN_SZ) bufBn[j] = xn;
        }
        nb = nb_next;
        __syncthreads();
    }

    if (hlast) {
        // final h written to buffer (T_STEPS & 1) == 0
        const float* bufA = hbuf;
        const float* bufB = hbuf + BUF_FLOATS;
        if (g == 0) hlast[b0 * HID + j] = bufA[IN_SZ + j];
        else        hlast[b1 * HID + j] = bufB[IN_SZ + j];
    }
}

extern "C" void kernel_launch(void* const* d_in, const int* in_sizes, int n_in,
                              void* d_out, int out_size)
{
    const float* x     = (const float*)d_in[0];   // [512,256,64]
    const float* h0    = (const float*)d_in[1];   // [256,256]
    const float* noise = (const float*)d_in[2];   // [512,256]
    const float* Win   = (const float*)d_in[3];   // [256,64]
    const float* bin   = (const float*)d_in[4];   // [256]
    const float* Whh   = (const float*)d_in[5];   // [256,256]
    const float* bhh   = (const float*)d_in[6];   // [256]

    const size_t TBH = (size_t)T_STEPS * BATCH * HID;
    const size_t BH  = (size_t)BATCH * HID;

    float* out   = nullptr;
    float* hlast = nullptr;
    if ((size_t)out_size >= TBH) {
        out = (float*)d_out;
        if ((size_t)out_size >= TBH + BH) hlast = (float*)d_out + TBH;
    } else {
        hlast = (float*)d_out;
    }

    static bool attr_set = false;
    if (!attr_set) {
        cudaFuncSetAttribute(ctrnn_ksplit_kernel,
                             cudaFuncAttributeMaxDynamicSharedMemorySize, SMEM_TOTAL);
        attr_set = true;
    }

    ctrnn_ksplit_kernel<<<NCTA, NTHR, SMEM_TOTAL>>>(
        x, h0, noise, Win, bin, Whh, bhh, out, hlast);
}